// round 4
// baseline (speedup 1.0000x reference)
#include <cuda_runtime.h>
#include <cuda_bf16.h>
#include <math.h>

// Problem constants
#define NROW 384          // N = 2*bs
#define BSZ  192
#define DIM  1024
#define NM1  383          // N-1
#define MDEN 56328576.0   // N*(N-1)^2

// Scratch (device globals; no allocation allowed)
__device__ float g_z[NROW * NROW];
__device__ float g_row[NROW];
__device__ int   g_cnt;          // zero-init; last block resets to 0 -> replay-safe

__device__ __forceinline__ const float* frow(const float* f, int r) {
    // feats row r: r<192 -> features[r,0,:]; else features[r-192,1,:]
    return f + (r < BSZ ? r * (2 * DIM) : (r - BSZ) * (2 * DIM) + DIM);
}

// ---------------------------------------------------------------------------
// Kernel 1: Gram + fused squared-norms -> pairwise L2 distances
//   z[i][j] = sqrt(max(sq_i + sq_j - 2*dot(i,j), 0))
// 32x32 output tile per block, grid 12x12 = 144 blocks (one wave on 148 SMs).
// Row/col squared norms are accumulated for free during the tile loads.
// ---------------------------------------------------------------------------
__global__ __launch_bounds__(256) void gram_kernel(const float* __restrict__ feats) {
    __shared__ float As[32][32];   // [k][row]
    __shared__ float Bs[32][32];   // [k][col]
    __shared__ float sqr[32], sqc[32];
    int tid = threadIdx.x;
    int r0 = blockIdx.y * 32, c0 = blockIdx.x * 32;
    int lr = tid & 31;     // row-in-tile for loads
    int kq = tid >> 5;     // 0..7 -> k-quad
    const float* arow = frow(feats, r0 + lr);
    const float* brow = frow(feats, c0 + lr);
    int ty = tid >> 4, tx = tid & 15;   // compute layout: 2x2 micro-tile
    float c00 = 0.f, c01 = 0.f, c10 = 0.f, c11 = 0.f;
    float sqa = 0.f, sqb = 0.f;

    for (int k0 = 0; k0 < DIM; k0 += 32) {
        float4 av = *(const float4*)(arow + k0 + kq * 4);
        float4 bv = *(const float4*)(brow + k0 + kq * 4);
        As[kq * 4 + 0][lr] = av.x; As[kq * 4 + 1][lr] = av.y;
        As[kq * 4 + 2][lr] = av.z; As[kq * 4 + 3][lr] = av.w;
        Bs[kq * 4 + 0][lr] = bv.x; Bs[kq * 4 + 1][lr] = bv.y;
        Bs[kq * 4 + 2][lr] = bv.z; Bs[kq * 4 + 3][lr] = bv.w;
        sqa = fmaf(av.x, av.x, sqa); sqa = fmaf(av.y, av.y, sqa);
        sqa = fmaf(av.z, av.z, sqa); sqa = fmaf(av.w, av.w, sqa);
        sqb = fmaf(bv.x, bv.x, sqb); sqb = fmaf(bv.y, bv.y, sqb);
        sqb = fmaf(bv.z, bv.z, sqb); sqb = fmaf(bv.w, bv.w, sqb);
        __syncthreads();
        #pragma unroll
        for (int kk = 0; kk < 32; kk++) {
            float2 a = *(const float2*)&As[kk][2 * ty];
            float2 b = *(const float2*)&Bs[kk][2 * tx];
            c00 = fmaf(a.x, b.x, c00);
            c01 = fmaf(a.x, b.y, c01);
            c10 = fmaf(a.y, b.x, c10);
            c11 = fmaf(a.y, b.y, c11);
        }
        __syncthreads();
    }
    // reduce sq partials: As/Bs free after last sync
    As[kq][lr] = sqa;
    Bs[kq][lr] = sqb;
    __syncthreads();
    if (tid < 32) {
        float s = 0.f;
        #pragma unroll
        for (int q = 0; q < 8; q++) s += As[q][tid];
        sqr[tid] = s;
    } else if (tid < 64) {
        int c = tid - 32;
        float s = 0.f;
        #pragma unroll
        for (int q = 0; q < 8; q++) s += Bs[q][c];
        sqc[c] = s;
    }
    __syncthreads();

    int r = r0 + 2 * ty, c = c0 + 2 * tx;
    float sr0 = sqr[2 * ty], sr1 = sqr[2 * ty + 1];
    float sc0 = sqc[2 * tx], sc1 = sqc[2 * tx + 1];
    g_z[r * NROW + c]           = sqrtf(fmaxf(sr0 + sc0 - 2.f * c00, 0.f));
    g_z[r * NROW + c + 1]       = sqrtf(fmaxf(sr0 + sc1 - 2.f * c01, 0.f));
    g_z[(r + 1) * NROW + c]     = sqrtf(fmaxf(sr1 + sc0 - 2.f * c10, 0.f));
    g_z[(r + 1) * NROW + c + 1] = sqrtf(fmaxf(sr1 + sc1 - 2.f * c11, 0.f));
}

// ---------------------------------------------------------------------------
// Kernel 2: per-row loss pieces + fused final reduction (last-block pattern).
// Per row i (block): build compacted off-diag arrays z,b (b = 0.1*dense_rank),
// counting-sort by label-diff (deterministic stable order), then:
//   rowsum = 2n*(Var-sums of z and b) - 4*Sum_{unordered}|dz*db|
//            + Sum_pos d*sigmoid(d-0.1) - Sum_pos d^2
// Cross term uses odd-n round-robin pairing: pairs {t, (t+r) mod 383},
// r = 1..191 enumerate every unordered pair exactly once, balanced load.
// ---------------------------------------------------------------------------
__device__ __forceinline__ float2 block_reduce2(float2 v, float2* red, int tid) {
    red[tid] = v;
    __syncthreads();
    #pragma unroll
    for (int s = 192; s >= 6; s >>= 1) {
        if (tid < s) {
            red[tid].x += red[tid + s].x;
            red[tid].y += red[tid + s].y;
        }
        __syncthreads();
    }
    if (tid == 0) {
        float2 r = red[0];
        #pragma unroll
        for (int q = 1; q < 6; q++) { r.x += red[q].x; r.y += red[q].y; }
        red[0] = r;
    }
    __syncthreads();
    float2 out = red[0];
    __syncthreads();
    return out;
}

__global__ __launch_bounds__(384) void row_kernel(const int* __restrict__ labels,
                                                  float* __restrict__ out) {
    __shared__ float2 zb[NROW];                 // sorted (z, b)
    __shared__ short  gsA[NROW], geA[NROW];     // group bounds per sorted pos
    __shared__ int    cntw[12][52];             // per-warp label-diff histogram
    __shared__ int    tot[52];
    __shared__ int    basev[53];
    __shared__ unsigned long long ymask;
    __shared__ float2 red2[NROW];
    __shared__ int    isLast;

    int tid = threadIdx.x;
    int i = blockIdx.x;
    int lane = tid & 31, wid = tid >> 5;
    bool valid = tid < NM1;

    // zero per-warp histograms + mask
    {
        int* cw = &cntw[0][0];
        for (int idx = tid; idx < 12 * 52; idx += 384) cw[idx] = 0;
        if (tid == 0) ymask = 0ull;
    }
    __syncthreads();

    int labi = labels[i >= BSZ ? i - BSZ : i];
    int yp = 0;
    float zp = 0.f;
    if (valid) {
        int j = tid + (tid >= i);
        zp = g_z[i * NROW + j];
        int labj = labels[j >= BSZ ? j - BSZ : j];
        yp = abs(labi - labj);                    // 0..49
        atomicOr(&ymask, 1ull << yp);
        atomicAdd(&cntw[wid][yp], 1);
    }
    __syncthreads();

    // dense rank via presence-bitmask popcount; b = 0.1*rank
    float bp = 0.1f * (float)__popcll(ymask & ((1ull << yp) - 1ull));

    // bin totals + exclusive scan
    if (tid < 52) {
        int s = 0;
        #pragma unroll
        for (int w2 = 0; w2 < 12; w2++) s += cntw[w2][tid];
        tot[tid] = s;
    }
    __syncthreads();
    if (tid == 0) {
        int run = 0;
        for (int v = 0; v < 52; v++) { basev[v] = run; run += tot[v]; }
        basev[52] = run;
    }
    __syncthreads();

    // deterministic stable position: bin base + earlier-warp count + within-warp rank
    unsigned mm = __match_any_sync(0xffffffffu, yp);
    int within = __popc(mm & ((1u << lane) - 1u));
    int before = 0;
    #pragma unroll
    for (int w2 = 0; w2 < 12; w2++)
        if (w2 < wid) before += cntw[w2][yp];
    if (valid) {
        int pos = basev[yp] + before + within;
        zb[pos] = make_float2(zp, bp);
        gsA[pos] = (short)basev[yp];
        geA[pos] = (short)(basev[yp] + tot[yp]);
    }
    __syncthreads();

    // closed-form variance sums (centered for fp32 safety)
    float2 s1 = block_reduce2(make_float2(valid ? zp : 0.f, valid ? bp : 0.f), red2, tid);
    float zm = s1.x * (1.0f / (float)NM1);
    float bm = s1.y * (1.0f / (float)NM1);
    float dzc = zp - zm, dbc = bp - bm;
    float2 s2 = block_reduce2(make_float2(valid ? dzc * dzc : 0.f,
                                          valid ? dbc * dbc : 0.f), red2, tid);

    // cross term, half-pair enumeration: thread t pairs with (t+1 .. t+191) mod 383
    float zj = 0.f, bj = 0.f;
    if (valid) { float2 t2 = zb[tid]; zj = t2.x; bj = t2.y; }
    float accC = 0.f;
    if (valid) {
        int hi = tid + (NM1 - 1) / 2;           // tid + 191
        int e1 = hi < NM1 - 1 ? hi : NM1 - 1;   // min(hi, 382)
        #pragma unroll 4
        for (int k = tid + 1; k <= e1; k++) {
            float2 v = zb[k];
            accC += fabsf((v.x - zj) * (v.y - bj));
        }
        int e2 = hi - NM1;                       // wrap portion
        #pragma unroll 4
        for (int k = 0; k <= e2; k++) {
            float2 v = zb[k];
            accC += fabsf((v.x - zj) * (v.y - bj));
        }
    }

    // pos correction: same-y pairs are the sorted group of j
    float accP = 0.f, accQ = 0.f;
    if (valid) {
        int g0 = gsA[tid], g1 = geA[tid];
        for (int kk = g0; kk < g1; kk++) {
            float d = fabsf(zb[kk].x - zj);
            accP += __fdividef(d, 1.0f + __expf(0.1f - d));
            accQ = fmaf(d, d, accQ);
        }
    }

    float2 s3 = block_reduce2(make_float2(accC, accP), red2, tid);
    float2 s4 = block_reduce2(make_float2(accQ, 0.f), red2, tid);

    if (tid == 0) {
        // 2n*(S2z+S2b) - 4*C_half + P - Q   (n = 383)
        float total = (2.0f * (float)NM1) * (s2.x + s2.y)
                    - 4.0f * s3.x + s3.y - s4.x;
        g_row[i] = total;
    }

    // ---- fused final reduction: last block sums all rows in double ----
    if (tid == 0) {
        __threadfence();
        int old = atomicAdd(&g_cnt, 1);
        isLast = (old == NROW - 1);
    }
    __syncthreads();
    if (isLast) {
        double* dred = (double*)red2;           // reuse smem (8B aligned)
        if (tid < 128) {
            dred[tid] = (double)g_row[tid] + (double)g_row[tid + 128]
                      + (double)g_row[tid + 256];
        }
        __syncthreads();
        #pragma unroll
        for (int st = 64; st > 0; st >>= 1) {
            if (tid < st) dred[tid] += dred[tid + st];
            __syncthreads();
        }
        if (tid == 0) {
            out[0] = (float)(dred[0] / MDEN);
            g_cnt = 0;                          // reset for graph replay
        }
    }
}

// ---------------------------------------------------------------------------
extern "C" void kernel_launch(void* const* d_in, const int* in_sizes, int n_in,
                              void* d_out, int out_size) {
    const float* features = (const float*)d_in[0];   // [192, 2, 1024] f32
    const int*   labels   = (const int*)d_in[1];     // [192, 1] i32
    (void)in_sizes; (void)n_in; (void)out_size;      // d_in[2] (ranks) unused

    gram_kernel<<<dim3(12, 12), 256>>>(features);
    row_kernel<<<NROW, 384>>>(labels, (float*)d_out);
}

// round 5
// speedup vs baseline: 1.6844x; 1.6844x over previous
#include <cuda_runtime.h>
#include <cuda_bf16.h>
#include <math.h>

// Problem constants
#define NROW 384          // N = 2*bs
#define BSZ  192
#define DIM  1024
#define NM1  383          // N-1
#define MDEN 56328576.0   // N*(N-1)^2
#define TK   48           // gram tile
#define NT   8            // tiles per side (384/48)

// Scratch (device globals; no allocation allowed)
__device__ float g_d[4][NROW * NROW];   // k-split partial dot products
__device__ float g_sqp[4 * NROW];       // k-split partial squared norms
__device__ float g_row[NROW];
__device__ int   g_cnt;                 // zero-init; last block resets -> replay-safe

__device__ __forceinline__ const float* frow(const float* f, int r) {
    return f + (r < BSZ ? r * (2 * DIM) : (r - BSZ) * (2 * DIM) + DIM);
}

// ---- packed f32x2 helpers (Blackwell) ----
__device__ __forceinline__ unsigned long long pk2(float lo, float hi) {
    unsigned long long r;
    asm("mov.b64 %0, {%1, %2};" : "=l"(r) : "f"(lo), "f"(hi));
    return r;
}
__device__ __forceinline__ unsigned long long add2(unsigned long long a, unsigned long long b) {
    unsigned long long r;
    asm("add.rn.f32x2 %0, %1, %2;" : "=l"(r) : "l"(a), "l"(b));
    return r;
}
__device__ __forceinline__ unsigned long long fma2p(unsigned long long a, unsigned long long b,
                                                    unsigned long long c) {
    unsigned long long r;
    asm("fma.rn.f32x2 %0, %1, %2, %3;" : "=l"(r) : "l"(a), "l"(b), "l"(c));
    return r;
}
__device__ __forceinline__ unsigned long long abs2(unsigned long long a) {
    return a & 0x7FFFFFFF7FFFFFFFULL;
}
__device__ __forceinline__ float lanesum(unsigned long long a) {
    float lo, hi;
    asm("mov.b64 {%0, %1}, %2;" : "=f"(lo), "=f"(hi) : "l"(a));
    return lo + hi;
}

// ---------------------------------------------------------------------------
// Kernel 1: symmetric tiled Gram partials with k-split.
// Grid = 36 tile-pairs * 4 k-slices = 144 blocks (one wave).
// Block handles tile (a,b), a<=b, k in [kz*256, kz*256+256); writes the tile
// and its transpose (bitwise-identical values -> deterministic), plus the
// diagonal (squared-norm) partials.
// ---------------------------------------------------------------------------
#define FMAK(cmp) \
    acc00 = fmaf(a0.cmp, b0v.cmp, acc00); acc01 = fmaf(a0.cmp, b1v.cmp, acc01); acc02 = fmaf(a0.cmp, b2v.cmp, acc02); \
    acc10 = fmaf(a1.cmp, b0v.cmp, acc10); acc11 = fmaf(a1.cmp, b1v.cmp, acc11); acc12 = fmaf(a1.cmp, b2v.cmp, acc12); \
    acc20 = fmaf(a2.cmp, b0v.cmp, acc20); acc21 = fmaf(a2.cmp, b1v.cmp, acc21); acc22 = fmaf(a2.cmp, b2v.cmp, acc22);

__global__ __launch_bounds__(256) void gram_kernel(const float* __restrict__ feats) {
    __shared__ float As[TK][68];     // [row][k]  (row-major, .128 reads, broadcast)
    __shared__ float BsT[64][49];    // [k][col]  (scalar reads, stride-3 conflict-free)

    int bid = blockIdx.x;
    int p = bid >> 2, kz = bid & 3;
    int a = 0, rem = p;
    while (rem >= NT - a) { rem -= NT - a; a++; }
    int b = a + rem;

    int tid = threadIdx.x;
    int ty = tid >> 4, tx = tid & 15;
    int r0 = a * TK, c0 = b * TK;
    int kbase = kz * 256;

    float acc00 = 0.f, acc01 = 0.f, acc02 = 0.f;
    float acc10 = 0.f, acc11 = 0.f, acc12 = 0.f;
    float acc20 = 0.f, acc21 = 0.f, acc22 = 0.f;

    for (int ch = 0; ch < 4; ch++) {
        int kc = kbase + ch * 64;
        #pragma unroll
        for (int it = 0; it < 3; it++) {
            int q = tid + it * 256;
            int r = q >> 4, kq = (q & 15) << 2;
            float4 av = *(const float4*)(frow(feats, r0 + r) + kc + kq);
            float4 bv = *(const float4*)(frow(feats, c0 + r) + kc + kq);
            *(float4*)&As[r][kq] = av;
            BsT[kq + 0][r] = bv.x; BsT[kq + 1][r] = bv.y;
            BsT[kq + 2][r] = bv.z; BsT[kq + 3][r] = bv.w;
        }
        __syncthreads();
        #pragma unroll
        for (int kk = 0; kk < 64; kk += 4) {
            float4 a0 = *(const float4*)&As[3 * ty + 0][kk];
            float4 a1 = *(const float4*)&As[3 * ty + 1][kk];
            float4 a2 = *(const float4*)&As[3 * ty + 2][kk];
            float4 b0v, b1v, b2v;
            b0v.x = BsT[kk + 0][3 * tx + 0]; b1v.x = BsT[kk + 0][3 * tx + 1]; b2v.x = BsT[kk + 0][3 * tx + 2];
            b0v.y = BsT[kk + 1][3 * tx + 0]; b1v.y = BsT[kk + 1][3 * tx + 1]; b2v.y = BsT[kk + 1][3 * tx + 2];
            b0v.z = BsT[kk + 2][3 * tx + 0]; b1v.z = BsT[kk + 2][3 * tx + 1]; b2v.z = BsT[kk + 2][3 * tx + 2];
            b0v.w = BsT[kk + 3][3 * tx + 0]; b1v.w = BsT[kk + 3][3 * tx + 1]; b2v.w = BsT[kk + 3][3 * tx + 2];
            FMAK(x) FMAK(y) FMAK(z) FMAK(w)
        }
        __syncthreads();
    }

    float accs[3][3] = {{acc00, acc01, acc02}, {acc10, acc11, acc12}, {acc20, acc21, acc22}};
    #pragma unroll
    for (int i2 = 0; i2 < 3; i2++) {
        #pragma unroll
        for (int j2 = 0; j2 < 3; j2++) {
            int r = r0 + 3 * ty + i2, c = c0 + 3 * tx + j2;
            float v = accs[i2][j2];
            g_d[kz][r * NROW + c] = v;
            g_d[kz][c * NROW + r] = v;
            if (r == c) g_sqp[kz * NROW + r] = v;
        }
    }
}

// ---------------------------------------------------------------------------
// block reduce float4: warp shuffle + one cross-warp stage (12 warps)
// ---------------------------------------------------------------------------
__device__ __forceinline__ float4 block_reduce4(float4 v, float* buf, int tid) {
    int lane = tid & 31, wid = tid >> 5;
    #pragma unroll
    for (int o = 16; o > 0; o >>= 1) {
        v.x += __shfl_xor_sync(0xffffffffu, v.x, o);
        v.y += __shfl_xor_sync(0xffffffffu, v.y, o);
        v.z += __shfl_xor_sync(0xffffffffu, v.z, o);
        v.w += __shfl_xor_sync(0xffffffffu, v.w, o);
    }
    if (lane == 0) ((float4*)buf)[wid] = v;
    __syncthreads();
    if (tid < 16) {
        float4 w = (tid < 12) ? ((float4*)buf)[tid] : make_float4(0.f, 0.f, 0.f, 0.f);
        #pragma unroll
        for (int o = 8; o > 0; o >>= 1) {
            w.x += __shfl_xor_sync(0xffffu, w.x, o);
            w.y += __shfl_xor_sync(0xffffu, w.y, o);
            w.z += __shfl_xor_sync(0xffffu, w.z, o);
            w.w += __shfl_xor_sync(0xffffu, w.w, o);
        }
        if (tid == 0) ((float4*)buf)[0] = w;
    }
    __syncthreads();
    float4 r = ((float4*)buf)[0];
    __syncthreads();
    return r;
}

// ---------------------------------------------------------------------------
// Kernel 2: per-row loss pieces + fused final reduction.
// rowsum = 2n*(S2z+S2b) - 4*C_half + P - Q
// Cross term: 2 j's per thread (j0=2t, j1=2t+1) share the k-window; packed
// f32x2; sign of db known per segment from the b-sorted order.
// ---------------------------------------------------------------------------
__global__ __launch_bounds__(384) void row_kernel(const int* __restrict__ labels,
                                                  float* __restrict__ out) {
    __shared__ float zEs[192], zOs[192], bEs[192], bOs[192];  // parity-split sorted
    __shared__ short gsA[NROW], geA[NROW];
    __shared__ int   cntw[12][52];
    __shared__ int   tot[52];
    __shared__ int   basev[53];
    __shared__ unsigned long long ymask;
    __shared__ float redbuf[64];
    __shared__ double dred[128];
    __shared__ int   isLast;

    int tid = threadIdx.x;
    int i = blockIdx.x;
    int lane = tid & 31, wid = tid >> 5;
    bool valid = tid < NM1;

    {
        int* cw = &cntw[0][0];
        for (int idx = tid; idx < 12 * 52; idx += 384) cw[idx] = 0;
        if (tid == 0) ymask = 0ull;
    }
    __syncthreads();

    int labi = labels[i >= BSZ ? i - BSZ : i];
    int yp = 0;
    float zp = 0.f;
    unsigned mm = 0;
    if (valid) {
        int jj = tid + (tid >= i);
        // reconstruct z from k-split partial dots + partial squared norms
        float dot = g_d[0][i * NROW + jj] + g_d[1][i * NROW + jj]
                  + g_d[2][i * NROW + jj] + g_d[3][i * NROW + jj];
        float sq_j = g_sqp[jj] + g_sqp[NROW + jj] + g_sqp[2 * NROW + jj] + g_sqp[3 * NROW + jj];
        float sq_i = g_sqp[i] + g_sqp[NROW + i] + g_sqp[2 * NROW + i] + g_sqp[3 * NROW + i];
        zp = sqrtf(fmaxf(sq_i + sq_j - 2.f * dot, 0.f));
        int labj = labels[jj >= BSZ ? jj - BSZ : jj];
        yp = abs(labi - labj);                    // 0..49
        atomicOr(&ymask, 1ull << yp);
        mm = __match_any_sync(__activemask(), yp);
        int leader = __ffs(mm) - 1;
        if (lane == leader) atomicAdd(&cntw[wid][yp], __popc(mm));
    }
    __syncthreads();

    float bp = 0.1f * (float)__popcll(ymask & ((1ull << yp) - 1ull));

    if (tid < 52) {
        int s = 0;
        #pragma unroll
        for (int w2 = 0; w2 < 12; w2++) s += cntw[w2][tid];
        tot[tid] = s;
    }
    __syncthreads();
    if (tid == 0) {
        int run = 0;
        for (int v = 0; v < 52; v++) { basev[v] = run; run += tot[v]; }
        basev[52] = run;
    }
    __syncthreads();

    if (valid) {
        int within = __popc(mm & ((1u << lane) - 1u));
        int before = 0;
        #pragma unroll
        for (int w2 = 0; w2 < 12; w2++)
            if (w2 < wid) before += cntw[w2][yp];
        int pos = basev[yp] + before + within;
        if (pos & 1) { zOs[pos >> 1] = zp; bOs[pos >> 1] = bp; }
        else         { zEs[pos >> 1] = zp; bEs[pos >> 1] = bp; }
        gsA[pos] = (short)basev[yp];
        geA[pos] = (short)(basev[yp] + tot[yp]);
    }
    __syncthreads();

#define ZAT(p) (((p) & 1) ? zOs[(p) >> 1] : zEs[(p) >> 1])
#define BAT(p) (((p) & 1) ? bOs[(p) >> 1] : bEs[(p) >> 1])

    // means (sum order = thread order, deterministic)
    float4 s1 = block_reduce4(make_float4(valid ? zp : 0.f, valid ? bp : 0.f, 0.f, 0.f),
                              redbuf, tid);
    float zm = s1.x * (1.0f / (float)NM1);
    float bm = s1.y * (1.0f / (float)NM1);
    float dzc = valid ? (zp - zm) : 0.f;
    float dbc = valid ? (bp - bm) : 0.f;
    float vsum = dzc * dzc + dbc * dbc;

    // ---- cross term: half-pair enumeration, 2 j's per thread, packed f32x2 ----
    float accC = 0.f;
    if (tid <= 190) {
        int t = tid;
        float zj0 = zEs[t], bj0 = bEs[t];     // j0 = 2t
        float zj1 = zOs[t], bj1 = bOs[t];     // j1 = 2t+1
        unsigned long long nz0 = pk2(-zj0, -zj0), nb0 = pk2(-bj0, -bj0);
        unsigned long long nz1 = pk2(-zj1, -zj1), nb1 = pk2(-bj1, -bj1);
        unsigned long long aP0 = 0ull, aP1 = 0ull, aN0 = 0ull, aN1 = 0ull;

        // Segment A (no wrap): k in [2t+2 .. min(382, 2t+191)], db >= 0
        int iAend = (t <= 95) ? (t + 95) : 190;
        #pragma unroll 2
        for (int q = t + 1; q <= iAend; q++) {
            unsigned long long zk2 = pk2(zEs[q], zOs[q]);
            unsigned long long bk2 = pk2(bEs[q], bOs[q]);
            aP0 = fma2p(add2(bk2, nb0), abs2(add2(zk2, nz0)), aP0);
            aP1 = fma2p(add2(bk2, nb1), abs2(add2(zk2, nz1)), aP1);
        }
        if (t >= 96) {
            // A single: k = 382
            float zk = zEs[191], bk = bEs[191];
            accC += (bk - bj0) * fabsf(zk - zj0);
            accC += (bk - bj1) * fabsf(zk - zj1);
            // Segment B (wrapped): k in [0 .. 2t-192], db <= 0
            #pragma unroll 2
            for (int q = 0; q <= t - 97; q++) {
                unsigned long long zk2 = pk2(zEs[q], zOs[q]);
                unsigned long long bk2 = pk2(bEs[q], bOs[q]);
                aN0 = fma2p(add2(bk2, nb0), abs2(add2(zk2, nz0)), aN0);
                aN1 = fma2p(add2(bk2, nb1), abs2(add2(zk2, nz1)), aN1);
            }
            // B single: k = 2t-192 (even)
            float zk2s = zEs[t - 96], bk2s = bEs[t - 96];
            accC += (bj0 - bk2s) * fabsf(zk2s - zj0);
            accC += (bj1 - bk2s) * fabsf(zk2s - zj1);
        }
        accC += lanesum(aP0) + lanesum(aP1) - lanesum(aN0) - lanesum(aN1);
        // edge (j0, j0+1)
        accC += (bj1 - bj0) * fabsf(zj1 - zj0);
        // edge (j1, j0+192 mod 383)
        {
            int k2 = (t <= 95) ? (2 * t + 192) : (2 * t - 191);
            float zk = ZAT(k2), bk = BAT(k2);
            accC += fabsf((zk - zj1) * (bk - bj1));
        }
        // redistributed pair (382, tid)
        {
            float zk = ZAT(tid), bk = BAT(tid);
            accC += fabsf((zEs[191] - zk) * (bEs[191] - bk));
        }
    }

    // ---- pos correction: same-y group of j ----
    float accP = 0.f, accQ = 0.f;
    if (valid) {
        float zj = ZAT(tid);
        int g0 = gsA[tid], g1 = geA[tid];
        for (int kk = g0; kk < g1; kk++) {
            float d = fabsf(ZAT(kk) - zj);
            accP += __fdividef(d, 1.0f + __expf(0.1f - d));
            accQ = fmaf(d, d, accQ);
        }
    }

    float4 s2 = block_reduce4(make_float4(vsum, accC, accP, accQ), redbuf, tid);

    if (tid == 0) {
        float total = (2.0f * (float)NM1) * s2.x - 4.0f * s2.y + s2.z - s2.w;
        g_row[i] = total;
    }

    // ---- fused final reduction: last block sums all rows (double tree) ----
    if (tid == 0) {
        __threadfence();
        int old = atomicAdd(&g_cnt, 1);
        isLast = (old == NROW - 1);
    }
    __syncthreads();
    if (isLast) {
        if (tid < 128) {
            dred[tid] = (double)g_row[tid] + (double)g_row[tid + 128]
                      + (double)g_row[tid + 256];
        }
        __syncthreads();
        #pragma unroll
        for (int st = 64; st > 0; st >>= 1) {
            if (tid < st) dred[tid] += dred[tid + st];
            __syncthreads();
        }
        if (tid == 0) {
            out[0] = (float)(dred[0] / MDEN);
            g_cnt = 0;                          // reset for graph replay
        }
    }
}

// ---------------------------------------------------------------------------
extern "C" void kernel_launch(void* const* d_in, const int* in_sizes, int n_in,
                              void* d_out, int out_size) {
    const float* features = (const float*)d_in[0];   // [192, 2, 1024] f32
    const int*   labels   = (const int*)d_in[1];     // [192, 1] i32
    (void)in_sizes; (void)n_in; (void)out_size;      // d_in[2] (ranks) unused

    gram_kernel<<<144, 256>>>(features);
    row_kernel<<<NROW, 384>>>(labels, (float*)d_out);
}

// round 7
// speedup vs baseline: 2.0327x; 1.2068x over previous
#include <cuda_runtime.h>
#include <cuda_bf16.h>
#include <math.h>

// Problem constants
#define NROW 384          // N = 2*bs
#define BSZ  192
#define DIM  1024
#define NM1  383          // N-1
#define MDEN 56328576.0   // N*(N-1)^2
#define TK   48           // gram tile
#define NT   8            // tiles per side (384/48)

// Scratch (device globals; no allocation allowed)
__device__ float g_d[4][NROW * NROW];   // k-split partial dot products
__device__ float g_sqp[4 * NROW];       // k-split partial squared norms
__device__ float g_row[NROW];
__device__ int   g_cnt;                 // zero-init; last block resets -> replay-safe

__device__ __forceinline__ const float* frow(const float* f, int r) {
    return f + (r < BSZ ? r * (2 * DIM) : (r - BSZ) * (2 * DIM) + DIM);
}

// ---- packed f32x2 helpers ----
__device__ __forceinline__ unsigned long long pk2(float lo, float hi) {
    unsigned long long r;
    asm("mov.b64 %0, {%1, %2};" : "=l"(r) : "f"(lo), "f"(hi));
    return r;
}
__device__ __forceinline__ unsigned long long add2(unsigned long long a, unsigned long long b) {
    unsigned long long r;
    asm("add.rn.f32x2 %0, %1, %2;" : "=l"(r) : "l"(a), "l"(b));
    return r;
}
__device__ __forceinline__ unsigned long long fma2p(unsigned long long a, unsigned long long b,
                                                    unsigned long long c) {
    unsigned long long r;
    asm("fma.rn.f32x2 %0, %1, %2, %3;" : "=l"(r) : "l"(a), "l"(b), "l"(c));
    return r;
}
__device__ __forceinline__ unsigned long long abs2(unsigned long long a) {
    return a & 0x7FFFFFFF7FFFFFFFULL;
}
__device__ __forceinline__ float lanesum(unsigned long long a) {
    float lo, hi;
    asm("mov.b64 {%0, %1}, %2;" : "=f"(lo), "=f"(hi) : "l"(a));
    return lo + hi;
}

// ---------------------------------------------------------------------------
// Kernel 1: symmetric tiled Gram partials with k-split.
// Grid = 36 tile-pairs * 4 k-slices = 144 blocks (one wave).
// ---------------------------------------------------------------------------
#define FMAK(cmp) \
    acc00 = fmaf(a0.cmp, b0v.cmp, acc00); acc01 = fmaf(a0.cmp, b1v.cmp, acc01); acc02 = fmaf(a0.cmp, b2v.cmp, acc02); \
    acc10 = fmaf(a1.cmp, b0v.cmp, acc10); acc11 = fmaf(a1.cmp, b1v.cmp, acc11); acc12 = fmaf(a1.cmp, b2v.cmp, acc12); \
    acc20 = fmaf(a2.cmp, b0v.cmp, acc20); acc21 = fmaf(a2.cmp, b1v.cmp, acc21); acc22 = fmaf(a2.cmp, b2v.cmp, acc22);

__global__ __launch_bounds__(256) void gram_kernel(const float* __restrict__ feats) {
    __shared__ float As[TK][68];
    __shared__ float BsT[64][49];

    int bid = blockIdx.x;
    int p = bid >> 2, kz = bid & 3;
    int a = 0, rem = p;
    while (rem >= NT - a) { rem -= NT - a; a++; }
    int b = a + rem;

    int tid = threadIdx.x;
    int ty = tid >> 4, tx = tid & 15;
    int r0 = a * TK, c0 = b * TK;
    int kbase = kz * 256;

    float acc00 = 0.f, acc01 = 0.f, acc02 = 0.f;
    float acc10 = 0.f, acc11 = 0.f, acc12 = 0.f;
    float acc20 = 0.f, acc21 = 0.f, acc22 = 0.f;

    for (int ch = 0; ch < 4; ch++) {
        int kc = kbase + ch * 64;
        #pragma unroll
        for (int it = 0; it < 3; it++) {
            int q = tid + it * 256;
            int r = q >> 4, kq = (q & 15) << 2;
            float4 av = *(const float4*)(frow(feats, r0 + r) + kc + kq);
            float4 bv = *(const float4*)(frow(feats, c0 + r) + kc + kq);
            *(float4*)&As[r][kq] = av;
            BsT[kq + 0][r] = bv.x; BsT[kq + 1][r] = bv.y;
            BsT[kq + 2][r] = bv.z; BsT[kq + 3][r] = bv.w;
        }
        __syncthreads();
        #pragma unroll
        for (int kk = 0; kk < 64; kk += 4) {
            float4 a0 = *(const float4*)&As[3 * ty + 0][kk];
            float4 a1 = *(const float4*)&As[3 * ty + 1][kk];
            float4 a2 = *(const float4*)&As[3 * ty + 2][kk];
            float4 b0v, b1v, b2v;
            b0v.x = BsT[kk + 0][3 * tx + 0]; b1v.x = BsT[kk + 0][3 * tx + 1]; b2v.x = BsT[kk + 0][3 * tx + 2];
            b0v.y = BsT[kk + 1][3 * tx + 0]; b1v.y = BsT[kk + 1][3 * tx + 1]; b2v.y = BsT[kk + 1][3 * tx + 2];
            b0v.z = BsT[kk + 2][3 * tx + 0]; b1v.z = BsT[kk + 2][3 * tx + 1]; b2v.z = BsT[kk + 2][3 * tx + 2];
            b0v.w = BsT[kk + 3][3 * tx + 0]; b1v.w = BsT[kk + 3][3 * tx + 1]; b2v.w = BsT[kk + 3][3 * tx + 2];
            FMAK(x) FMAK(y) FMAK(z) FMAK(w)
        }
        __syncthreads();
    }

    float accs[3][3] = {{acc00, acc01, acc02}, {acc10, acc11, acc12}, {acc20, acc21, acc22}};
    #pragma unroll
    for (int i2 = 0; i2 < 3; i2++) {
        #pragma unroll
        for (int j2 = 0; j2 < 3; j2++) {
            int r = r0 + 3 * ty + i2, c = c0 + 3 * tx + j2;
            float v = accs[i2][j2];
            g_d[kz][r * NROW + c] = v;
            g_d[kz][c * NROW + r] = v;
            if (r == c) g_sqp[kz * NROW + r] = v;
        }
    }
}

// ---------------------------------------------------------------------------
// block reduce float4 for 192 threads (6 warps)
// ---------------------------------------------------------------------------
__device__ __forceinline__ float4 bred4(float4 v, float4* buf, int tid) {
    int lane = tid & 31, wid = tid >> 5;
    #pragma unroll
    for (int o = 16; o > 0; o >>= 1) {
        v.x += __shfl_xor_sync(0xffffffffu, v.x, o);
        v.y += __shfl_xor_sync(0xffffffffu, v.y, o);
        v.z += __shfl_xor_sync(0xffffffffu, v.z, o);
        v.w += __shfl_xor_sync(0xffffffffu, v.w, o);
    }
    if (lane == 0) buf[wid] = v;
    __syncthreads();
    if (tid < 8) {
        float4 w = (tid < 6) ? buf[tid] : make_float4(0.f, 0.f, 0.f, 0.f);
        #pragma unroll
        for (int o = 4; o > 0; o >>= 1) {
            w.x += __shfl_xor_sync(0xffu, w.x, o);
            w.y += __shfl_xor_sync(0xffu, w.y, o);
            w.z += __shfl_xor_sync(0xffu, w.z, o);
            w.w += __shfl_xor_sync(0xffu, w.w, o);
        }
        if (tid == 0) buf[0] = w;
    }
    __syncthreads();
    float4 r = buf[0];
    __syncthreads();
    return r;
}

// ---------------------------------------------------------------------------
// Kernel 2: 192 threads/block, one row per block, all 384 blocks resident.
// Each thread owns elements p0=tid, p1=tid+192 for setup, and the j-pair
// (2t, 2t+1) for the cross term over the extended pair array (no wrap).
// rowsum = 2n*(S2z+S2b) - 4*C_half + P - Q
// ---------------------------------------------------------------------------
__global__ __launch_bounds__(192) void row_kernel(const int* __restrict__ labels,
                                                  float* __restrict__ out) {
    __shared__ float4 ext4[288];                // (z_a, z_{a+1}, b_a, b_{a+1})
    __shared__ float  zs[NM1], bs[NM1];         // sorted scalars
    __shared__ short  gsA[NM1], geA[NM1];       // group bounds per sorted pos
    __shared__ int    cntw[12][52];             // 12 virtual warp slots
    __shared__ int    tot[52];
    __shared__ int    basev[52];
    __shared__ unsigned long long ymask;
    __shared__ float4 redbuf[6];
    __shared__ double dred[128];
    __shared__ int    isLast;

    int tid = threadIdx.x;
    int i = blockIdx.x;
    int lane = tid & 31, wid = tid >> 5;
    bool v1 = tid < 191;                        // second element valid

    {
        int* cw = &cntw[0][0];
        for (int idx = tid; idx < 12 * 52; idx += 192) cw[idx] = 0;
        if (tid == 0) ymask = 0ull;
    }
    __syncthreads();

    int labi = labels[i >= BSZ ? i - BSZ : i];
    float sq_i = g_sqp[i] + g_sqp[NROW + i] + g_sqp[2 * NROW + i] + g_sqp[3 * NROW + i];

    // ---- element 0: p0 = tid (always valid) ----
    float z0; int y0;
    {
        int jj = tid + (tid >= i);
        float dot = g_d[0][i * NROW + jj] + g_d[1][i * NROW + jj]
                  + g_d[2][i * NROW + jj] + g_d[3][i * NROW + jj];
        float sq_j = g_sqp[jj] + g_sqp[NROW + jj] + g_sqp[2 * NROW + jj] + g_sqp[3 * NROW + jj];
        z0 = sqrtf(fmaxf(sq_i + sq_j - 2.f * dot, 0.f));
        int labj = labels[jj >= BSZ ? jj - BSZ : jj];
        y0 = abs(labi - labj);
    }
    // ---- element 1: p1 = tid + 192 ----
    float z1 = 0.f; int y1 = 0;
    if (v1) {
        int p1 = tid + 192;
        int jj = p1 + (p1 >= i);
        float dot = g_d[0][i * NROW + jj] + g_d[1][i * NROW + jj]
                  + g_d[2][i * NROW + jj] + g_d[3][i * NROW + jj];
        float sq_j = g_sqp[jj] + g_sqp[NROW + jj] + g_sqp[2 * NROW + jj] + g_sqp[3 * NROW + jj];
        z1 = sqrtf(fmaxf(sq_i + sq_j - 2.f * dot, 0.f));
        int labj = labels[jj >= BSZ ? jj - BSZ : jj];
        y1 = abs(labi - labj);
    }

    atomicOr(&ymask, (1ull << y0) | (v1 ? (1ull << y1) : 0ull));

    unsigned mm0 = __match_any_sync(0xffffffffu, y0);
    if (lane == __ffs(mm0) - 1) atomicAdd(&cntw[wid][y0], __popc(mm0));
    unsigned mm1 = 0;
    if (v1) {
        mm1 = __match_any_sync(__activemask(), y1);
        if (lane == __ffs(mm1) - 1) atomicAdd(&cntw[6 + wid][y1], __popc(mm1));
    }
    __syncthreads();

    float bp0 = 0.1f * (float)__popcll(ymask & ((1ull << y0) - 1ull));
    float bp1 = 0.1f * (float)__popcll(ymask & ((1ull << y1) - 1ull));

    if (tid < 52) {
        int s = 0;
        #pragma unroll
        for (int w2 = 0; w2 < 12; w2++) s += cntw[w2][tid];
        tot[tid] = s;
    }
    __syncthreads();
    if (tid == 0) {
        int run = 0;
        for (int v = 0; v < 52; v++) { basev[v] = run; run += tot[v]; }
    }
    __syncthreads();

    // scatter element 0 (virtual warp = wid)
    {
        int before = 0;
        #pragma unroll
        for (int w2 = 0; w2 < 6; w2++)
            if (w2 < wid) before += cntw[w2][y0];
        int pos = basev[y0] + before + __popc(mm0 & ((1u << lane) - 1u));
        zs[pos] = z0; bs[pos] = bp0;
        gsA[pos] = (short)basev[y0];
        geA[pos] = (short)(basev[y0] + tot[y0]);
    }
    // scatter element 1 (virtual warp = 6 + wid)
    if (v1) {
        int before = 0;
        #pragma unroll
        for (int w2 = 0; w2 < 6; w2++) before += cntw[w2][y1];
        #pragma unroll
        for (int w2 = 6; w2 < 12; w2++)
            if (w2 < 6 + wid) before += cntw[w2][y1];
        int pos = basev[y1] + before + __popc(mm1 & ((1u << lane) - 1u));
        zs[pos] = z1; bs[pos] = bp1;
        gsA[pos] = (short)basev[y1];
        geA[pos] = (short)(basev[y1] + tot[y1]);
    }
    __syncthreads();

    // ---- build extended pair array: ext[q] covers elements (2q, 2q+1) mod 383
    {
        int a = 2 * tid; if (a >= NM1) a -= NM1;      // q = tid (a<=382)
        int b2 = a + 1;  if (b2 >= NM1) b2 -= NM1;
        ext4[tid] = make_float4(zs[a], zs[b2], bs[a], bs[b2]);
    }
    if (tid < 96) {
        int q = tid + 192;
        int a = 2 * q - NM1;                           // odd, 1..191
        ext4[q] = make_float4(zs[a], zs[a + 1], bs[a], bs[a + 1]);
    }
    __syncthreads();

    // ---- means + variance contributions ----
    float4 s1 = bred4(make_float4(z0 + (v1 ? z1 : 0.f), bp0 + (v1 ? bp1 : 0.f), 0.f, 0.f),
                      redbuf, tid);
    float zm = s1.x * (1.0f / (float)NM1);
    float bm = s1.y * (1.0f / (float)NM1);
    float dz0 = z0 - zm, db0 = bp0 - bm;
    float vsum = dz0 * dz0 + db0 * db0;
    if (v1) {
        float dz1 = z1 - zm, db1 = bp1 - bm;
        vsum += dz1 * dz1 + db1 * db1;
    }

    // ---- cross term: j0=2t, j1=2t+1 share 95 extended pairs [t+1 .. t+95] ----
    float accC = 0.f;
    if (tid <= 190) {
        int t = tid;
        float zj0 = zs[2 * t],     bj0 = bs[2 * t];
        float zj1 = zs[2 * t + 1], bj1 = bs[2 * t + 1];
        unsigned long long nz0 = pk2(-zj0, -zj0), nb0 = pk2(-bj0, -bj0);
        unsigned long long nz1 = pk2(-zj1, -zj1), nb1 = pk2(-bj1, -bj1);
        unsigned long long aA = 0ull, aB = 0ull;
        unsigned int addr = (unsigned int)__cvta_generic_to_shared(&ext4[t + 1]);
        #pragma unroll 5
        for (int q = 0; q < 95; q++) {
            unsigned long long zk2, bk2;
            asm("ld.shared.v2.b64 {%0, %1}, [%2];" : "=l"(zk2), "=l"(bk2) : "r"(addr));
            addr += 16;
            aA = fma2p(abs2(add2(zk2, nz0)), abs2(add2(bk2, nb0)), aA);
            aB = fma2p(abs2(add2(zk2, nz1)), abs2(add2(bk2, nb1)), aB);
        }
        accC = lanesum(aA) + lanesum(aB);
        // edge pair (j0, j1)
        accC += fabsf((zj1 - zj0) * (bj1 - bj0));
        // trailing single for j1: element 2t+192 (mod 383)
        {
            int ke = 2 * t + 192; if (ke >= NM1) ke -= NM1;
            accC += fabsf((zs[ke] - zj1) * (bs[ke] - bj1));
        }
        // redistributed pair (382, t)
        accC += fabsf((zs[382] - zs[t]) * (bs[382] - bs[t]));
    }

    // ---- pos correction: same-y groups of p0 and p1 ----
    float accP = 0.f, accQ = 0.f;
    {
        float zj = zs[tid];
        int g0 = gsA[tid], g1 = geA[tid];
        for (int kk = g0; kk < g1; kk++) {
            float d = fabsf(zs[kk] - zj);
            accP += __fdividef(d, 1.0f + __expf(0.1f - d));
            accQ = fmaf(d, d, accQ);
        }
    }
    if (v1) {
        int p1 = tid + 192;
        float zj = zs[p1];
        int g0 = gsA[p1], g1 = geA[p1];
        for (int kk = g0; kk < g1; kk++) {
            float d = fabsf(zs[kk] - zj);
            accP += __fdividef(d, 1.0f + __expf(0.1f - d));
            accQ = fmaf(d, d, accQ);
        }
    }

    float4 s2 = bred4(make_float4(vsum, accC, accP, accQ), redbuf, tid);

    if (tid == 0) {
        float total = (2.0f * (float)NM1) * s2.x - 4.0f * s2.y + s2.z - s2.w;
        g_row[i] = total;
    }

    // ---- fused final reduction ----
    if (tid == 0) {
        __threadfence();
        int old = atomicAdd(&g_cnt, 1);
        isLast = (old == NROW - 1);
    }
    __syncthreads();
    if (isLast) {
        if (tid < 128) {
            dred[tid] = (double)g_row[tid] + (double)g_row[tid + 128]
                      + (double)g_row[tid + 256];
        }
        __syncthreads();
        #pragma unroll
        for (int st = 64; st > 0; st >>= 1) {
            if (tid < st) dred[tid] += dred[tid + st];
            __syncthreads();
        }
        if (tid == 0) {
            out[0] = (float)(dred[0] / MDEN);
            g_cnt = 0;                          // reset for graph replay
        }
    }
}

// ---------------------------------------------------------------------------
extern "C" void kernel_launch(void* const* d_in, const int* in_sizes, int n_in,
                              void* d_out, int out_size) {
    const float* features = (const float*)d_in[0];   // [192, 2, 1024] f32
    const int*   labels   = (const int*)d_in[1];     // [192, 1] i32
    (void)in_sizes; (void)n_in; (void)out_size;      // d_in[2] (ranks) unused

    gram_kernel<<<144, 256>>>(features);
    row_kernel<<<NROW, 192>>>(labels, (float*)d_out);
}